// round 9
// baseline (speedup 1.0000x reference)
#include <cuda_runtime.h>
#include <cuda_fp16.h>

#define B 32
#define R 5
#define C 100
#define C4 25     // c-quarter
#define N 101
#define NPAD 104
#define H 128
#define E 5
#define F 13      // 8 + R
#define TN 8      // nodes per einsum tile
#define NT 13     // ceil(N / TN)
#define TG 16     // nodes per gemm tile
#define NG 7      // ceil(N / TG)

// ---------------- scratch (device globals; no allocations allowed) ----------
__device__ __half g_pemb[(size_t)B * N * C * H];       // 82.7 MB, fp16
__device__ float  g_pres[(size_t)B * C * N];           // presence [B,C,N]
__device__ float  g_fx  [(size_t)B * N * H];           // fx1 then fx2
__device__ float  g_ua  [(size_t)B * N * H];           // message-passing state
__device__ float  g_l   [4 * (size_t)B * NPAD * H];    // einsum partials (4 c-quarters)

__device__ __forceinline__ __half2 tanh2_fast(__half2 x) {
    unsigned xi = *(unsigned*)&x, yi;
    asm("tanh.approx.f16x2 %0, %1;" : "=r"(yi) : "r"(xi));
    return *(__half2*)&yi;
}

// ---------------- features: x -> fx1, u = relu(fx1 + bl1) -------------------
__global__ void k_features(const float* __restrict__ ap, const float* __restrict__ act,
                           const float* __restrict__ xa, const float* __restrict__ xb,
                           const float* __restrict__ coord, const float* __restrict__ avail,
                           const float* __restrict__ wx1, const float* __restrict__ bx1,
                           const float* __restrict__ bl1)
{
    int b = blockIdx.x / N, n = blockIdx.x % N;
    __shared__ float xs[F];
    int tid = threadIdx.x;
    if (tid < 5) {
        float s = 0.f;
        #pragma unroll
        for (int r = 0; r < R; r++) {
            int idx = (b * R + r) * N + n;
            float a = ap[idx] + act[idx];
            s = fmaf(a, xa[idx * R + tid], s);
        }
        xs[tid] = s;
    } else if (tid < 10) {
        xs[tid] = xb[(b * N + n) * 5 + tid - 5];
    } else if (tid < 12) {
        xs[tid] = coord[(b * N + n) * 2 + tid - 10];
    } else if (tid == 12) {
        xs[12] = avail[b * N + n];
    }
    __syncthreads();
    int h = tid;
    float acc = bx1[h];
    #pragma unroll
    for (int k = 0; k < F; k++) acc = fmaf(xs[k], wx1[k * H + h], acc);
    int o = (b * N + n) * H + h;
    g_fx[o] = acc;
    g_ua[o] = fmaxf(acc + bl1[h], 0.f);
}

// ---------------- presence head: softmax over n per (b,c) -------------------
__global__ void k_presence(const float* __restrict__ edge, const float* __restrict__ avail,
                           const float* __restrict__ w1p, const float* __restrict__ b1p,
                           const float* __restrict__ w2p, const float* __restrict__ b2p)
{
    int b = blockIdx.x / C, c = blockIdx.x % C;
    __shared__ float w1s[E * H], b1s[H], w2s[H], lg[N], red[H];
    int tid = threadIdx.x;
    for (int i = tid; i < E * H; i += H) w1s[i] = w1p[i];
    b1s[tid] = b1p[tid];
    w2s[tid] = w2p[tid];
    __syncthreads();

    float lgv = -3.4e38f;
    if (tid < N) {
        int n = tid;
        const float* e5 = edge + ((size_t)(b * C + c) * N + n) * E;
        float e0 = e5[0], e1 = e5[1], e2 = e5[2], e3 = e5[3], e4 = e5[4];
        float s = 0.f;
        #pragma unroll 4
        for (int h = 0; h < H; h++) {
            float a = b1s[h];
            a = fmaf(e0, w1s[h], a);
            a = fmaf(e1, w1s[H + h], a);
            a = fmaf(e2, w1s[2 * H + h], a);
            a = fmaf(e3, w1s[3 * H + h], a);
            a = fmaf(e4, w1s[4 * H + h], a);
            s = fmaf(fmaxf(a, 0.f), w2s[h], s);
        }
        s = s + b2p[0];                  // TAU = 1
        float m = avail[b * N + n];
        if (n == c || n == N - 1) m = 0.f;
        lgv = s * m - (1.f - m) * 1e10f;
        lg[n] = lgv;
    }
    red[tid] = lgv;
    __syncthreads();
    for (int s2 = 64; s2 > 0; s2 >>= 1) {
        if (tid < s2) red[tid] = fmaxf(red[tid], red[tid + s2]);
        __syncthreads();
    }
    float mx = red[0];
    __syncthreads();
    float p = 0.f;
    if (tid < N) p = __expf(lg[tid] - mx);
    red[tid] = p;
    __syncthreads();
    for (int s2 = 64; s2 > 0; s2 >>= 1) {
        if (tid < s2) red[tid] += red[tid + s2];
        __syncthreads();
    }
    float inv = 1.f / red[0];
    if (tid < N) {
        float availc = avail[b * N + c];
        g_pres[(size_t)(b * C + c) * N + tid] = availc * p * inv;
    }
}

// ---------------- fused: build pemb (fp16) AND first einsum sweep -----------
// grid = B*26 (4 nodes per CTA), block 512. Writes l into quarter 0 of g_l.
__global__ void k_pemb_fused(const float* __restrict__ edge, const float* __restrict__ we,
                             const float* __restrict__ be)
{
    int b = blockIdx.x / 26, g = blockIdx.x % 26;
    extern __shared__ char sm[];
    float2* us  = (float2*)sm;                           // 100*64 float2 = 51200 B
    float*  es  = (float*)(sm + 51200);                  // 4*100*5      =  8000 B
    float*  ps  = (float*)(sm + 59200);                  // 4*100        =  1600 B
    float2* wes = (float2*)(sm + 60800);                 // 5*64 float2  =  2560 B
    float2* bes = (float2*)(sm + 63360);                 // 64 float2    =   512 B
    float2* ls  = (float2*)(sm + 63872);                 // 4*64 float2  =  2048 B
    int tid = threadIdx.x;

    const float4* u4 = (const float4*)g_ua + (size_t)b * N * 32;
    float4* us4p = (float4*)us;
    for (int i = tid; i < C * 32; i += 512) us4p[i] = u4[i];
    if (tid < 64) {
        #pragma unroll
        for (int e = 0; e < E; e++)
            wes[e * 64 + tid] = make_float2(we[e * H + 2 * tid], we[e * H + 2 * tid + 1]);
        bes[tid] = make_float2(be[2 * tid], be[2 * tid + 1]);
    }
    for (int i = tid; i < 4 * C * E; i += 512) {
        int nl = i / (C * E), rem = i % (C * E), c = rem / E, e = rem % E;
        int n = min(g * 4 + nl, N - 1);
        es[i] = edge[(((size_t)b * C + c) * N + n) * E + e];
    }
    for (int i = tid; i < 4 * C; i += 512) {
        int nl = i / C, c = i % C;
        int n = min(g * 4 + nl, N - 1);
        ps[i] = g_pres[((size_t)b * C + c) * N + n];
    }
    __syncthreads();

    int lt = tid & 127, nl = tid >> 7;
    int h2 = lt & 63, co = lt >> 6;
    int n = g * 4 + nl;
    int nc = min(n, N - 1);
    float2 bb = bes[h2];
    float lx = 0.f, ly = 0.f;
    __half2* out = (__half2*)g_pemb + ((size_t)(b * N + nc) * C) * 64 + h2;
    const float* esn = es + nl * (C * E);
    const float* psn = ps + nl * C;

    for (int c = co; c < C; c += 2) {
        float a0 = bb.x, a1 = bb.y;
        #pragma unroll
        for (int e = 0; e < E; e++) {
            float ev = esn[c * E + e];
            float2 w = wes[e * 64 + h2];
            a0 = fmaf(ev, w.x, a0);
            a1 = fmaf(ev, w.y, a1);
        }
        __half2 t = tanh2_fast(__floats2half2_rn(a0, a1));
        __half2 pe = __hmul2(t, __float2half2_rn(psn[c]));
        if (n < N) out[(size_t)c * 64] = pe;
        float2 pf = __half22float2(pe);
        float2 uv = us[c * 64 + h2];
        lx = fmaf(pf.x, uv.x, lx);
        ly = fmaf(pf.y, uv.y, ly);
    }
    if (co == 1) ls[nl * 64 + h2] = make_float2(lx, ly);
    __syncthreads();
    if (co == 0 && n < N) {
        float2 o = ls[nl * 64 + h2];
        ((float2*)g_l)[((size_t)b * NPAD + n) * 64 + h2] =
            make_float2(lx + o.x, ly + o.y);
    }
}

// ---------------- einsum (c-quarter): l_q[b,n,h] = sum_{c in q} pemb*u ------
// grid = B*NT*4, block 256. warp = node; half-warp loads full 256B pemb row.
__global__ void __launch_bounds__(256) k_einsum()
{
    int id = blockIdx.x;
    int q = id & 3, nt = (id >> 2) % NT, b = id / (4 * NT);
    extern __shared__ float4 us4[];            // C4*32 float4 = 12800 B
    int tid = threadIdx.x;

    const float4* u4 = (const float4*)g_ua + ((size_t)b * N + q * C4) * 32;
    for (int i = tid; i < C4 * 32; i += 256) us4[i] = u4[i];
    __syncthreads();

    int lane = tid & 31, nl = tid >> 5;
    int n = nt * TN + nl;
    int nc = min(n, N - 1);
    int sub = lane >> 4, l16 = lane & 15;

    const uint4* pp = (const uint4*)g_pemb +
                      ((size_t)(b * N + nc) * C + q * C4) * 16 + l16;
    float a0 = 0.f, a1 = 0.f, a2 = 0.f, a3 = 0.f;
    float a4 = 0.f, a5 = 0.f, a6 = 0.f, a7 = 0.f;
    #pragma unroll
    for (int i = 0; i < 12; i++) {
        int c = 2 * i + sub;
        uint4 pv = pp[(size_t)c * 16];
        float4 ua = us4[c * 32 + l16 * 2];
        float4 ub = us4[c * 32 + l16 * 2 + 1];
        float2 p0 = __half22float2(*(__half2*)&pv.x);
        float2 p1 = __half22float2(*(__half2*)&pv.y);
        float2 p2 = __half22float2(*(__half2*)&pv.z);
        float2 p3 = __half22float2(*(__half2*)&pv.w);
        a0 = fmaf(p0.x, ua.x, a0); a1 = fmaf(p0.y, ua.y, a1);
        a2 = fmaf(p1.x, ua.z, a2); a3 = fmaf(p1.y, ua.w, a3);
        a4 = fmaf(p2.x, ub.x, a4); a5 = fmaf(p2.y, ub.y, a5);
        a6 = fmaf(p3.x, ub.z, a6); a7 = fmaf(p3.y, ub.w, a7);
    }
    if (sub == 0) {                            // tail c = 24
        const int c = 24;
        uint4 pv = pp[(size_t)c * 16];
        float4 ua = us4[c * 32 + l16 * 2];
        float4 ub = us4[c * 32 + l16 * 2 + 1];
        float2 p0 = __half22float2(*(__half2*)&pv.x);
        float2 p1 = __half22float2(*(__half2*)&pv.y);
        float2 p2 = __half22float2(*(__half2*)&pv.z);
        float2 p3 = __half22float2(*(__half2*)&pv.w);
        a0 = fmaf(p0.x, ua.x, a0); a1 = fmaf(p0.y, ua.y, a1);
        a2 = fmaf(p1.x, ua.z, a2); a3 = fmaf(p1.y, ua.w, a3);
        a4 = fmaf(p2.x, ub.x, a4); a5 = fmaf(p2.y, ub.y, a5);
        a6 = fmaf(p3.x, ub.z, a6); a7 = fmaf(p3.y, ub.w, a7);
    }
    a0 += __shfl_xor_sync(0xffffffffu, a0, 16);
    a1 += __shfl_xor_sync(0xffffffffu, a1, 16);
    a2 += __shfl_xor_sync(0xffffffffu, a2, 16);
    a3 += __shfl_xor_sync(0xffffffffu, a3, 16);
    a4 += __shfl_xor_sync(0xffffffffu, a4, 16);
    a5 += __shfl_xor_sync(0xffffffffu, a5, 16);
    a6 += __shfl_xor_sync(0xffffffffu, a6, 16);
    a7 += __shfl_xor_sync(0xffffffffu, a7, 16);
    if (sub == 0 && n < N) {
        float4* lo = (float4*)g_l + (((size_t)q * B + b) * NPAD + n) * 32 + l16 * 2;
        lo[0] = make_float4(a0, a1, a2, a3);
        lo[1] = make_float4(a4, a5, a6, a7);
    }
}

// ---------------- u = relu((sum_q l_q) @ wl + bl + fx) ----------------------
// grid = B*NG (224), block 128. wl in fp16 smem; 2 nodes x 8 h per thread.
template<int NPARTS>
__global__ void __launch_bounds__(128) k_lgemm(const float* __restrict__ wl,
                                               const float* __restrict__ bl)
{
    int b = blockIdx.x / NG, nt = blockIdx.x % NG;
    int base = nt * TG;
    __shared__ __half wlh[H * H];        // 32768 B
    __shared__ float  ls[TG * H];        // 8192 B
    int tid = threadIdx.x;

    const float4* w4 = (const float4*)wl;
    #pragma unroll
    for (int i = tid; i < H * H / 4; i += 128) {
        float4 v = w4[i];
        ((__half2*)wlh)[2 * i]     = __floats2half2_rn(v.x, v.y);
        ((__half2*)wlh)[2 * i + 1] = __floats2half2_rn(v.z, v.w);
    }
    #pragma unroll
    for (int i = tid; i < TG * 32; i += 128) {
        int nl = i >> 5, j = i & 31;
        int n = base + nl;
        float4 v = make_float4(0.f, 0.f, 0.f, 0.f);
        if (n < N) {
            #pragma unroll
            for (int q = 0; q < NPARTS; q++) {
                float4 x = ((const float4*)g_l)[(((size_t)q * B + b) * NPAD + n) * 32 + j];
                v.x += x.x; v.y += x.y; v.z += x.z; v.w += x.w;
            }
        }
        ((float4*)ls)[i] = v;
    }
    __syncthreads();

    int hg = tid & 15, np = tid >> 4;
    int h0 = hg * 8, nl0 = np * 2;
    float a0[8], a1[8];
    #pragma unroll
    for (int k = 0; k < 8; k++) { a0[k] = 0.f; a1[k] = 0.f; }

    #pragma unroll 4
    for (int hp = 0; hp < H; hp++) {
        uint4 wv = *(const uint4*)&wlh[hp * H + h0];
        float l0 = ls[nl0 * H + hp];
        float l1 = ls[(nl0 + 1) * H + hp];
        float2 w0 = __half22float2(*(__half2*)&wv.x);
        float2 w1 = __half22float2(*(((__half2*)&wv.x) + 1));
        float2 w2 = __half22float2(*(__half2*)&wv.z);
        float2 w3 = __half22float2(*(((__half2*)&wv.z) + 1));
        a0[0] = fmaf(l0, w0.x, a0[0]); a1[0] = fmaf(l1, w0.x, a1[0]);
        a0[1] = fmaf(l0, w0.y, a0[1]); a1[1] = fmaf(l1, w0.y, a1[1]);
        a0[2] = fmaf(l0, w1.x, a0[2]); a1[2] = fmaf(l1, w1.x, a1[2]);
        a0[3] = fmaf(l0, w1.y, a0[3]); a1[3] = fmaf(l1, w1.y, a1[3]);
        a0[4] = fmaf(l0, w2.x, a0[4]); a1[4] = fmaf(l1, w2.x, a1[4]);
        a0[5] = fmaf(l0, w2.y, a0[5]); a1[5] = fmaf(l1, w2.y, a1[5]);
        a0[6] = fmaf(l0, w3.x, a0[6]); a1[6] = fmaf(l1, w3.x, a1[6]);
        a0[7] = fmaf(l0, w3.y, a0[7]); a1[7] = fmaf(l1, w3.y, a1[7]);
    }

    float4 bA = *(const float4*)&bl[h0];
    float4 bB = *(const float4*)&bl[h0 + 4];
    int n0 = base + nl0, n1 = n0 + 1;
    if (n0 < N) {
        const float* fx = &g_fx[((size_t)b * N + n0) * H + h0];
        float4 fA = *(const float4*)fx, fB = *(const float4*)(fx + 4);
        float* o = &g_ua[((size_t)b * N + n0) * H + h0];
        *(float4*)o = make_float4(fmaxf(a0[0] + bA.x + fA.x, 0.f), fmaxf(a0[1] + bA.y + fA.y, 0.f),
                                  fmaxf(a0[2] + bA.z + fA.z, 0.f), fmaxf(a0[3] + bA.w + fA.w, 0.f));
        *(float4*)(o + 4) = make_float4(fmaxf(a0[4] + bB.x + fB.x, 0.f), fmaxf(a0[5] + bB.y + fB.y, 0.f),
                                        fmaxf(a0[6] + bB.z + fB.z, 0.f), fmaxf(a0[7] + bB.w + fB.w, 0.f));
    }
    if (n1 < N) {
        const float* fx = &g_fx[((size_t)b * N + n1) * H + h0];
        float4 fA = *(const float4*)fx, fB = *(const float4*)(fx + 4);
        float* o = &g_ua[((size_t)b * N + n1) * H + h0];
        *(float4*)o = make_float4(fmaxf(a1[0] + bA.x + fA.x, 0.f), fmaxf(a1[1] + bA.y + fA.y, 0.f),
                                  fmaxf(a1[2] + bA.z + fA.z, 0.f), fmaxf(a1[3] + bA.w + fA.w, 0.f));
        *(float4*)(o + 4) = make_float4(fmaxf(a1[4] + bB.x + fB.x, 0.f), fmaxf(a1[5] + bB.y + fB.y, 0.f),
                                        fmaxf(a1[6] + bB.z + fB.z, 0.f), fmaxf(a1[7] + bB.w + fB.w, 0.f));
    }
}

// ---------------- fx2 = u@wx2+bx2; gamma_init = relu(fx2+bl2) ---------------
// same tiling as k_lgemm; input u from g_ua, writes g_fx and g_ua.
__global__ void __launch_bounds__(128) k_fx2(const float* __restrict__ wx2,
                                             const float* __restrict__ bx2,
                                             const float* __restrict__ bl2)
{
    int b = blockIdx.x / NG, nt = blockIdx.x % NG;
    int base = nt * TG;
    __shared__ __half wxh[H * H];
    __shared__ float  us[TG * H];
    int tid = threadIdx.x;

    const float4* w4 = (const float4*)wx2;
    #pragma unroll
    for (int i = tid; i < H * H / 4; i += 128) {
        float4 v = w4[i];
        ((__half2*)wxh)[2 * i]     = __floats2half2_rn(v.x, v.y);
        ((__half2*)wxh)[2 * i + 1] = __floats2half2_rn(v.z, v.w);
    }
    #pragma unroll
    for (int i = tid; i < TG * 32; i += 128) {
        int nl = i >> 5, j = i & 31;
        int n = base + nl;
        float4 v = make_float4(0.f, 0.f, 0.f, 0.f);
        if (n < N) v = ((const float4*)g_ua)[((size_t)b * N + n) * 32 + j];
        ((float4*)us)[i] = v;
    }
    __syncthreads();

    int hg = tid & 15, np = tid >> 4;
    int h0 = hg * 8, nl0 = np * 2;
    float a0[8], a1[8];
    #pragma unroll
    for (int k = 0; k < 8; k++) { a0[k] = 0.f; a1[k] = 0.f; }

    #pragma unroll 4
    for (int hp = 0; hp < H; hp++) {
        uint4 wv = *(const uint4*)&wxh[hp * H + h0];
        float l0 = us[nl0 * H + hp];
        float l1 = us[(nl0 + 1) * H + hp];
        float2 w0 = __half22float2(*(__half2*)&wv.x);
        float2 w1 = __half22float2(*(((__half2*)&wv.x) + 1));
        float2 w2 = __half22float2(*(__half2*)&wv.z);
        float2 w3 = __half22float2(*(((__half2*)&wv.z) + 1));
        a0[0] = fmaf(l0, w0.x, a0[0]); a1[0] = fmaf(l1, w0.x, a1[0]);
        a0[1] = fmaf(l0, w0.y, a0[1]); a1[1] = fmaf(l1, w0.y, a1[1]);
        a0[2] = fmaf(l0, w1.x, a0[2]); a1[2] = fmaf(l1, w1.x, a1[2]);
        a0[3] = fmaf(l0, w1.y, a0[3]); a1[3] = fmaf(l1, w1.y, a1[3]);
        a0[4] = fmaf(l0, w2.x, a0[4]); a1[4] = fmaf(l1, w2.x, a1[4]);
        a0[5] = fmaf(l0, w2.y, a0[5]); a1[5] = fmaf(l1, w2.y, a1[5]);
        a0[6] = fmaf(l0, w3.x, a0[6]); a1[6] = fmaf(l1, w3.x, a1[6]);
        a0[7] = fmaf(l0, w3.y, a0[7]); a1[7] = fmaf(l1, w3.y, a1[7]);
    }

    float4 xA = *(const float4*)&bx2[h0];
    float4 xB = *(const float4*)&bx2[h0 + 4];
    float4 bA = *(const float4*)&bl2[h0];
    float4 bB = *(const float4*)&bl2[h0 + 4];
    int n0 = base + nl0, n1 = n0 + 1;
    if (n0 < N) {
        float* fo = &g_fx[((size_t)b * N + n0) * H + h0];
        float* uo = &g_ua[((size_t)b * N + n0) * H + h0];
        float4 fA = make_float4(a0[0] + xA.x, a0[1] + xA.y, a0[2] + xA.z, a0[3] + xA.w);
        float4 fB = make_float4(a0[4] + xB.x, a0[5] + xB.y, a0[6] + xB.z, a0[7] + xB.w);
        *(float4*)fo = fA; *(float4*)(fo + 4) = fB;
        *(float4*)uo = make_float4(fmaxf(fA.x + bA.x, 0.f), fmaxf(fA.y + bA.y, 0.f),
                                   fmaxf(fA.z + bA.z, 0.f), fmaxf(fA.w + bA.w, 0.f));
        *(float4*)(uo + 4) = make_float4(fmaxf(fB.x + bB.x, 0.f), fmaxf(fB.y + bB.y, 0.f),
                                         fmaxf(fB.z + bB.z, 0.f), fmaxf(fB.w + bB.w, 0.f));
    }
    if (n1 < N) {
        float* fo = &g_fx[((size_t)b * N + n1) * H + h0];
        float* uo = &g_ua[((size_t)b * N + n1) * H + h0];
        float4 fA = make_float4(a1[0] + xA.x, a1[1] + xA.y, a1[2] + xA.z, a1[3] + xA.w);
        float4 fB = make_float4(a1[4] + xB.x, a1[5] + xB.y, a1[6] + xB.z, a1[7] + xB.w);
        *(float4*)fo = fA; *(float4*)(fo + 4) = fB;
        *(float4*)uo = make_float4(fmaxf(fA.x + bA.x, 0.f), fmaxf(fA.y + bA.y, 0.f),
                                   fmaxf(fA.z + bA.z, 0.f), fmaxf(fA.w + bA.w, 0.f));
        *(float4*)(uo + 4) = make_float4(fmaxf(fB.x + bB.x, 0.f), fmaxf(fB.y + bB.y, 0.f),
                                         fmaxf(fB.z + bB.z, 0.f), fmaxf(fB.w + bB.w, 0.f));
    }
}

// ---------------- Q readout --------------------------------------------------
__global__ void k_reduce(const float* __restrict__ avail, const float* __restrict__ wQ,
                         float* __restrict__ out)
{
    int b = blockIdx.x;
    int h = threadIdx.x;
    float s = 0.f;
    for (int n = 0; n < N; n++)
        s = fmaf(g_ua[(b * N + n) * H + h], avail[b * N + n], s);
    s *= wQ[h];
    __shared__ float red[H];
    red[h] = s;
    __syncthreads();
    for (int s2 = 64; s2 > 0; s2 >>= 1) {
        if (h < s2) red[h] += red[h + s2];
        __syncthreads();
    }
    if (h == 0) out[b] = red[0];
}

// ---------------- launch -----------------------------------------------------
extern "C" void kernel_launch(void* const* d_in, const int* in_sizes, int n_in,
                              void* d_out, int out_size)
{
    const float* ap    = (const float*)d_in[0];
    const float* act   = (const float*)d_in[1];
    const float* xa    = (const float*)d_in[2];
    const float* xb    = (const float*)d_in[3];
    const float* coord = (const float*)d_in[4];
    const float* edge  = (const float*)d_in[5];
    const float* avail = (const float*)d_in[6];
    const float* w1p   = (const float*)d_in[7];
    const float* b1p   = (const float*)d_in[8];
    const float* w2p   = (const float*)d_in[9];
    const float* b2p   = (const float*)d_in[10];
    const float* wx1   = (const float*)d_in[11];
    const float* bx1   = (const float*)d_in[12];
    const float* we1   = (const float*)d_in[13];
    const float* be1   = (const float*)d_in[14];
    const float* wl1   = (const float*)d_in[15];
    const float* bl1   = (const float*)d_in[16];
    const float* wx2   = (const float*)d_in[17];
    const float* bx2   = (const float*)d_in[18];
    const float* we2   = (const float*)d_in[19];
    const float* be2   = (const float*)d_in[20];
    const float* wl2   = (const float*)d_in[21];
    const float* bl2   = (const float*)d_in[22];
    const float* wQ    = (const float*)d_in[23];
    float* out = (float*)d_out;

    const int fu_smem = 65920;                      // k_pemb_fused
    const int es_smem = C4 * 32 * 16;               // 12800 B
    cudaFuncSetAttribute(k_pemb_fused, cudaFuncAttributeMaxDynamicSharedMemorySize, fu_smem);
    cudaFuncSetAttribute(k_einsum, cudaFuncAttributeMaxDynamicSharedMemorySize, es_smem);

    k_features<<<B * N, H>>>(ap, act, xa, xb, coord, avail, wx1, bx1, bl1);
    k_presence<<<B * C, H>>>(edge, avail, w1p, b1p, w2p, b2p);

    // round 1: iter1 folded into k_features; iter2 fused with pemb build
    k_pemb_fused<<<B * 26, 512, fu_smem>>>(edge, we1, be1);
    k_lgemm<1><<<B * NG, 128>>>(wl1, bl1);
    for (int t = 0; t < 3; t++) {
        k_einsum<<<B * NT * 4, 256, es_smem>>>();
        k_lgemm<4><<<B * NG, 128>>>(wl1, bl1);
    }

    // round 2
    k_fx2<<<B * NG, 128>>>(wx2, bx2, bl2);
    k_pemb_fused<<<B * 26, 512, fu_smem>>>(edge, we2, be2);
    k_lgemm<1><<<B * NG, 128>>>(wl2, bl2);
    for (int t = 0; t < 3; t++) {
        k_einsum<<<B * NT * 4, 256, es_smem>>>();
        k_lgemm<4><<<B * NG, 128>>>(wl2, bl2);
    }

    k_reduce<<<B, H>>>(avail, wQ, out);
}